// round 5
// baseline (speedup 1.0000x reference)
#include <cuda_runtime.h>
#include <math.h>

#define BB 64
#define NL 256
#define EE 512
#define DD 512
#define UU 512

#define NROWS_LEAF (BB*NL)   // 16384
#define NROWS_LVL  16320     // sum over levels 1..8 of B*(256>>l)

// ---- scratch (device globals; no allocation allowed) ----
__device__ float g_leaf_h[NROWS_LEAF*DD];     // 33.5 MB
__device__ float g_levels[NROWS_LVL*DD];      // 33.4 MB, levels 1..8 packed
__device__ float g_mr[NROWS_LVL];
__device__ float g_ctrl_s[BB];
__device__ float g_ctrl_T[BB];
__device__ float g_ctrl_Wh[BB*DD];
__device__ float g_attn[NROWS_LEAF];
__device__ float g_upd[NROWS_LEAF];
__device__ float g_tree_out[BB*EE];
__device__ float g_z[BB*4*UU];

__constant__ int c_lvl_off[10] = {0, 0, 8192, 12288, 14336, 15360, 15872, 16128, 16256, 16320};
__constant__ int c_lvl_m[9]   = {0, 128, 64, 32, 16, 8, 4, 2, 1};

__device__ __forceinline__ float sigmoidf_(float x) { return 1.0f / (1.0f + expf(-x)); }

// ============================================================================
// Tiled fp32 GEMM: C[M,N] = act(A[M,K] @ B[K,N])
// BM=BN=64, BK=16, 256 threads, 4x4 per thread. M,N multiples of 64; K of 16.
// MODE 0: raw   MODE 1: relu   MODE 2: fused write-update epilogue -> d_out
// ============================================================================
template<int MODE>
__global__ void __launch_bounds__(256)
gemm_kernel(float* __restrict__ C, const float* __restrict__ A,
            const float* __restrict__ Bmat, int N, int K)
{
    __shared__ float As[16][64];
    __shared__ float Bs[16][64];
    const int tid = threadIdx.x;
    const int tx  = tid & 15;
    const int ty  = tid >> 4;
    const int bm  = blockIdx.y, bn = blockIdx.x;

    const int arow = tid >> 2;          // 0..63
    const int acol = (tid & 3) << 2;    // 0,4,8,12
    const int brow = tid >> 4;          // 0..15
    const int bcol = (tid & 15) << 2;   // 0..60

    const float* Ab = A + (size_t)bm * 64 * K;
    const float* Bb = Bmat + bn * 64;

    float acc[4][4];
    #pragma unroll
    for (int i = 0; i < 4; i++)
        #pragma unroll
        for (int j = 0; j < 4; j++) acc[i][j] = 0.0f;

    for (int k0 = 0; k0 < K; k0 += 16) {
        float4 av = *reinterpret_cast<const float4*>(Ab + (size_t)arow * K + k0 + acol);
        As[acol + 0][arow] = av.x;
        As[acol + 1][arow] = av.y;
        As[acol + 2][arow] = av.z;
        As[acol + 3][arow] = av.w;
        float4 bv = *reinterpret_cast<const float4*>(Bb + (size_t)(k0 + brow) * N + bcol);
        *reinterpret_cast<float4*>(&Bs[brow][bcol]) = bv;
        __syncthreads();

        #pragma unroll
        for (int kk = 0; kk < 16; kk++) {
            float4 a = *reinterpret_cast<const float4*>(&As[kk][ty << 2]);
            float4 b = *reinterpret_cast<const float4*>(&Bs[kk][tx << 2]);
            float ar[4] = {a.x, a.y, a.z, a.w};
            float br[4] = {b.x, b.y, b.z, b.w};
            #pragma unroll
            for (int i = 0; i < 4; i++)
                #pragma unroll
                for (int j = 0; j < 4; j++)
                    acc[i][j] = fmaf(ar[i], br[j], acc[i][j]);
        }
        __syncthreads();
    }

    #pragma unroll
    for (int i = 0; i < 4; i++) {
        int row = bm * 64 + (ty << 2) + i;
        #pragma unroll
        for (int j = 0; j < 4; j++) {
            int col = bn * 64 + (tx << 2) + j;
            float v = acc[i][j];
            if (MODE == 1) v = fmaxf(v, 0.0f);
            if (MODE == 2) {
                int b      = row >> 8;                         // 256 leaves per batch
                float cand = sigmoidf_(v + g_ctrl_Wh[b * DD + col]);
                float u    = g_upd[row];
                float lh   = g_leaf_h[(size_t)row * DD + col];
                float w    = u * cand + (1.0f - u) * lh;
                float a    = g_attn[row];
                v = a * w + (1.0f - a) * lh;
            }
            C[(size_t)row * N + col] = v;
        }
    }
}

// ---- per-batch control dot products: ctrl.W_s[512:], ctrl.W_T[512:] ----
__global__ void ctrl_kernel(const float* __restrict__ h0,
                            const float* __restrict__ Ws,
                            const float* __restrict__ WT)
{
    int b = blockIdx.x;
    int lane = threadIdx.x;   // 32 threads
    float s1 = 0.0f, s2 = 0.0f;
    for (int u = lane; u < UU; u += 32) {
        float h = h0[b * UU + u];
        s1 += h * Ws[DD + u];
        s2 += h * WT[DD + u];
    }
    #pragma unroll
    for (int o = 16; o; o >>= 1) {
        s1 += __shfl_xor_sync(0xffffffffu, s1, o);
        s2 += __shfl_xor_sync(0xffffffffu, s2, o);
    }
    if (lane == 0) { g_ctrl_s[b] = s1; g_ctrl_T[b] = s2; }
}

// ---- search gates mr for all 255*B internal nodes (warp per node) ----
__global__ void mr_kernel(const float* __restrict__ Ws)
{
    int gw = (blockIdx.x * blockDim.x + threadIdx.x) >> 5;
    int lane = threadIdx.x & 31;
    if (gw >= NROWS_LVL) return;
    const float* row = g_levels + (size_t)gw * DD;
    float s = 0.0f;
    #pragma unroll 4
    for (int k = lane; k < DD; k += 32) s += row[k] * Ws[k];
    #pragma unroll
    for (int o = 16; o; o >>= 1) s += __shfl_xor_sync(0xffffffffu, s, o);
    if (lane == 0) {
        int l = 1;
        #pragma unroll
        for (int i = 2; i <= 8; i++) if (gw >= c_lvl_off[i]) l = i;
        int b = (gw - c_lvl_off[l]) / c_lvl_m[l];
        g_mr[gw] = sigmoidf_(s + g_ctrl_s[b]);
    }
}

// ---- leaf attention: product of 8 path-gate factors ----
__global__ void attn_kernel()
{
    int b = blockIdx.x;
    int leaf = threadIdx.x;   // 256 threads
    float a = 1.0f;
    #pragma unroll
    for (int l = 1; l <= 8; l++) {
        int m = NL >> l;
        int j = leaf >> l;
        int c = leaf >> (l - 1);
        float mr = g_mr[c_lvl_off[l] + b * m + j];
        a *= (c & 1) ? mr : (1.0f - mr);
    }
    g_attn[b * NL + leaf] = a;
}

// ---- tree_out[b,e] = sum_n attn[b,n] * inputs[b,n,e] ----
__global__ void treeout_kernel(const float* __restrict__ inputs)
{
    __shared__ float sa[NL];
    int b = blockIdx.x;
    int e = threadIdx.x;      // 512 threads
    if (e < NL) sa[e] = g_attn[b * NL + e];
    __syncthreads();
    float s = 0.0f;
    const float* base = inputs + (size_t)b * NL * EE + e;
    #pragma unroll 4
    for (int n = 0; n < NL; n++) s += sa[n] * base[(size_t)n * EE];
    g_tree_out[b * EE + e] = s;
}

// ---- write gate upd per leaf row (warp per row) ----
__global__ void upd_kernel(const float* __restrict__ WT)
{
    int gw = (blockIdx.x * blockDim.x + threadIdx.x) >> 5;
    int lane = threadIdx.x & 31;
    if (gw >= NROWS_LEAF) return;
    const float* row = g_leaf_h + (size_t)gw * DD;
    float s = 0.0f;
    #pragma unroll 4
    for (int k = lane; k < DD; k += 32) s += row[k] * WT[k];
    #pragma unroll
    for (int o = 16; o; o >>= 1) s += __shfl_xor_sync(0xffffffffu, s, o);
    if (lane == 0) g_upd[gw] = sigmoidf_(s + g_ctrl_T[gw >> 8]);
}

// ---- LSTM pre-activations z = tree_out@kernel + h0@rec_kernel + bias ----
__global__ void lstmz_kernel(const float* __restrict__ h0,
                             const float* __restrict__ kern,
                             const float* __restrict__ rec,
                             const float* __restrict__ bias)
{
    int b = blockIdx.y;
    int o = blockIdx.x * blockDim.x + threadIdx.x;   // 0..2047
    float s = bias[o];
    const float* to = g_tree_out + b * EE;
    const float* hh = h0 + b * UU;
    #pragma unroll 4
    for (int k = 0; k < EE; k++) s = fmaf(to[k], kern[(size_t)k * (4 * UU) + o], s);
    #pragma unroll 4
    for (int k = 0; k < UU; k++) s = fmaf(hh[k], rec[(size_t)k * (4 * UU) + o], s);
    g_z[b * 4 * UU + o] = s;
}

// ---- LSTM gates -> h_new, c_new ----
__global__ void lstmgate_kernel(const float* __restrict__ c0,
                                float* __restrict__ out_h,
                                float* __restrict__ out_c)
{
    int b = blockIdx.x;
    int u = threadIdx.x;      // 512 threads
    float zi = g_z[b * 2048 + u];
    float zf = g_z[b * 2048 + 512 + u];
    float zg = g_z[b * 2048 + 1024 + u];
    float zo = g_z[b * 2048 + 1536 + u];
    float c = sigmoidf_(zf) * c0[b * UU + u] + sigmoidf_(zi) * tanhf(zg);
    float h = sigmoidf_(zo) * tanhf(c);
    out_h[b * UU + u] = h;
    out_c[b * UU + u] = c;
}

// ============================================================================
extern "C" void kernel_launch(void* const* d_in, const int* in_sizes, int n_in,
                              void* d_out, int out_size)
{
    const float* inputs = (const float*)d_in[0];
    const float* h0     = (const float*)d_in[1];
    const float* c0     = (const float*)d_in[2];
    const float* W_t    = (const float*)d_in[3];
    const float* W_j    = (const float*)d_in[4];
    const float* W_s    = (const float*)d_in[5];
    const float* W_h    = (const float*)d_in[6];
    const float* W_T    = (const float*)d_in[7];
    const float* kern   = (const float*)d_in[8];
    const float* rec    = (const float*)d_in[9];
    const float* bias   = (const float*)d_in[10];

    float* out      = (float*)d_out;
    float* out_h    = out;                    // [64,512]
    float* out_c    = out + BB * UU;          // [64,512]
    float* out_leaf = out + 2 * BB * UU;      // [64,256,512]

    float *p_leaf, *p_levels, *p_ctrlWh;
    cudaGetSymbolAddress((void**)&p_leaf,   g_leaf_h);
    cudaGetSymbolAddress((void**)&p_levels, g_levels);
    cudaGetSymbolAddress((void**)&p_ctrlWh, g_ctrl_Wh);

    dim3 blk(256);
    const int lvl_off[10] = {0, 0, 8192, 12288, 14336, 15360, 15872, 16128, 16256, 16320};

    // 1) leaf embed: relu(inputs @ W_t)   [16384,512] x [512,512]
    gemm_kernel<1><<<dim3(DD / 64, NROWS_LEAF / 64), blk>>>(p_leaf, inputs, W_t, DD, EE);

    // 2) bottom-up joins: pair-concat == reinterpret [m,512] as [m/2,1024]
    const float* src = p_leaf;
    for (int l = 1; l <= 8; l++) {
        int Mrows = BB * (NL >> l);
        float* dst = p_levels + (size_t)lvl_off[l] * DD;
        gemm_kernel<1><<<dim3(DD / 64, Mrows / 64), blk>>>(dst, src, W_j, DD, 2 * DD);
        src = dst;
    }

    // 3) per-batch control terms (independent — depend only on h0, weights)
    ctrl_kernel<<<BB, 32>>>(h0, W_s, W_T);
    gemm_kernel<0><<<dim3(DD / 64, BB / 64), blk>>>(p_ctrlWh, h0, W_h + DD * DD, DD, UU);

    // 4) search gates for all internal nodes, then leaf attentions
    mr_kernel<<<(NROWS_LVL * 32 + 255) / 256, 256>>>(W_s);
    attn_kernel<<<BB, NL>>>();

    // 5) soft retrieval
    treeout_kernel<<<BB, EE>>>(inputs);

    // 6) write gates + fused write-update GEMM straight into d_out
    upd_kernel<<<(NROWS_LEAF * 32 + 255) / 256, 256>>>(W_T);
    gemm_kernel<2><<<dim3(DD / 64, NROWS_LEAF / 64), blk>>>(out_leaf, p_leaf, W_h, DD, DD);

    // 7) LSTM cell
    lstmz_kernel<<<dim3(4 * UU / 256, BB), 256>>>(h0, kern, rec, bias);
    lstmgate_kernel<<<BB, UU>>>(c0, out_h, out_c);
}

// round 7
// speedup vs baseline: 1.3231x; 1.3231x over previous
#include <cuda_runtime.h>
#include <math.h>

#define BB 64
#define NL 256
#define EE 512
#define DD 512
#define UU 512

#define NROWS_LEAF (BB*NL)   // 16384
#define NROWS_LVL  16320     // sum over levels 1..8 of B*(256>>l)

// ---- scratch (device globals; no allocation allowed) ----
__device__ float g_leaf_h[NROWS_LEAF*DD];     // 33.5 MB
__device__ float g_levels[NROWS_LVL*DD];      // 33.4 MB, levels 1..8 packed
__device__ float g_part[8388608];             // 32 MB split-K partials
                                              // (max use: lvl2 S=4*M4096*N512 = 8388608)
__device__ float g_mr[NROWS_LVL];
__device__ float g_ctrl_s[BB];
__device__ float g_ctrl_T[BB];
__device__ float g_ctrl_Wh[BB*DD];
__device__ float g_attn[NROWS_LEAF];
__device__ float g_upd[NROWS_LEAF];
__device__ float g_tree_out[BB*EE];
__device__ float g_z[BB*4*UU];

__constant__ int c_lvl_off[10] = {0, 0, 8192, 12288, 14336, 15360, 15872, 16128, 16256, 16320};
__constant__ int c_lvl_m[9]   = {0, 128, 64, 32, 16, 8, 4, 2, 1};

__device__ __forceinline__ float sigmoidf_(float x) { return 1.0f / (1.0f + expf(-x)); }

#define MODE_RAW   0
#define MODE_RELU  1
#define MODE_WRITE 2
#define MODE_PART  3

// ============================================================================
// 128x128x16 double-buffered fp32 GEMM, 8x8 micro-tile, 256 threads.
// C[M,N] = act(A[M,K] @ B[K,N]) over K range [z*kChunk, (z+1)*kChunk).
// N % 128 == 0, kChunk % 16 == 0. M row-guarded (may be < gridDim.y*128).
// MODE_PART writes raw partials at C + z*M*N + r*N + c.
// ============================================================================
template<int MODE>
__global__ void __launch_bounds__(256, 2)
gemm128(float* __restrict__ C, const float* __restrict__ A,
        const float* __restrict__ Bmat, int M, int N, int K, int kChunk)
{
    __shared__ float As[2][16][136];   // +8 pad de-conflicts strided STS
    __shared__ float Bs[2][16][128];

    const int tid  = threadIdx.x;
    const int row0 = blockIdx.y * 128;
    const int col0 = blockIdx.x * 128;

    const int ty = tid >> 4;          // rows ty*8..+7
    const int tx = tid & 15;          // cols tx*8..+7

    const int a_r = tid >> 1;         // 0..127
    const int a_k = (tid & 1) * 8;    // 0 or 8
    const int b_k = tid >> 4;         // 0..15
    const int b_n = (tid & 15) * 8;   // 0..120

    const int  kBeg  = blockIdx.z * kChunk;
    const int  nIter = kChunk >> 4;
    const bool a_ok  = (row0 + a_r) < M;

    const float* Aptr = A + (size_t)(row0 + a_r) * K + kBeg + a_k;
    const float* Bptr = Bmat + (size_t)(kBeg + b_k) * N + col0 + b_n;

    float acc[8][8];
    #pragma unroll
    for (int i = 0; i < 8; i++)
        #pragma unroll
        for (int j = 0; j < 8; j++) acc[i][j] = 0.0f;

    float a_st[8], b_st[8];

    // ---- prologue: stage 0 ----
    {
        float4 v0, v1;
        if (a_ok) { v0 = *(const float4*)(Aptr); v1 = *(const float4*)(Aptr + 4); }
        else      { v0 = make_float4(0,0,0,0);   v1 = v0; }
        a_st[0]=v0.x; a_st[1]=v0.y; a_st[2]=v0.z; a_st[3]=v0.w;
        a_st[4]=v1.x; a_st[5]=v1.y; a_st[6]=v1.z; a_st[7]=v1.w;
        float4 w0 = *(const float4*)(Bptr);
        float4 w1 = *(const float4*)(Bptr + 4);
        b_st[0]=w0.x; b_st[1]=w0.y; b_st[2]=w0.z; b_st[3]=w0.w;
        b_st[4]=w1.x; b_st[5]=w1.y; b_st[6]=w1.z; b_st[7]=w1.w;
    }
    #pragma unroll
    for (int i = 0; i < 8; i++) As[0][a_k + i][a_r] = a_st[i];
    *(float4*)&Bs[0][b_k][b_n]     = make_float4(b_st[0], b_st[1], b_st[2], b_st[3]);
    *(float4*)&Bs[0][b_k][b_n + 4] = make_float4(b_st[4], b_st[5], b_st[6], b_st[7]);
    __syncthreads();

    int buf = 0;
    for (int t = 0; t < nIter; t++) {
        if (t + 1 < nIter) {
            float4 v0, v1;
            if (a_ok) { v0 = *(const float4*)(Aptr + (t+1)*16);
                        v1 = *(const float4*)(Aptr + (t+1)*16 + 4); }
            else      { v0 = make_float4(0,0,0,0); v1 = v0; }
            a_st[0]=v0.x; a_st[1]=v0.y; a_st[2]=v0.z; a_st[3]=v0.w;
            a_st[4]=v1.x; a_st[5]=v1.y; a_st[6]=v1.z; a_st[7]=v1.w;
            float4 w0 = *(const float4*)(Bptr + (size_t)(t+1)*16*N);
            float4 w1 = *(const float4*)(Bptr + (size_t)(t+1)*16*N + 4);
            b_st[0]=w0.x; b_st[1]=w0.y; b_st[2]=w0.z; b_st[3]=w0.w;
            b_st[4]=w1.x; b_st[5]=w1.y; b_st[6]=w1.z; b_st[7]=w1.w;
        }

        #pragma unroll
        for (int kk = 0; kk < 16; kk++) {
            float a[8], b[8];
            *(float4*)(a)     = *(const float4*)&As[buf][kk][ty*8];
            *(float4*)(a + 4) = *(const float4*)&As[buf][kk][ty*8 + 4];
            *(float4*)(b)     = *(const float4*)&Bs[buf][kk][tx*8];
            *(float4*)(b + 4) = *(const float4*)&Bs[buf][kk][tx*8 + 4];
            #pragma unroll
            for (int i = 0; i < 8; i++)
                #pragma unroll
                for (int j = 0; j < 8; j++)
                    acc[i][j] = fmaf(a[i], b[j], acc[i][j]);
        }

        if (t + 1 < nIter) {
            #pragma unroll
            for (int i = 0; i < 8; i++) As[buf^1][a_k + i][a_r] = a_st[i];
            *(float4*)&Bs[buf^1][b_k][b_n]     = make_float4(b_st[0], b_st[1], b_st[2], b_st[3]);
            *(float4*)&Bs[buf^1][b_k][b_n + 4] = make_float4(b_st[4], b_st[5], b_st[6], b_st[7]);
        }
        __syncthreads();
        buf ^= 1;
    }

    // ---- epilogue ----
    float* Cbase = C;
    if (MODE == MODE_PART) Cbase = C + (size_t)blockIdx.z * M * N;

    #pragma unroll
    for (int i = 0; i < 8; i++) {
        int r = row0 + ty*8 + i;
        if (r < M) {
            float* crow = Cbase + (size_t)r * N + col0 + tx*8;
            if (MODE == MODE_WRITE) {
                int bb = r >> 8;
                float u  = g_upd[r];
                float at = g_attn[r];
                #pragma unroll
                for (int h = 0; h < 8; h += 4) {
                    int col = col0 + tx*8 + h;
                    float4 lh = *(const float4*)&g_leaf_h[(size_t)r * DD + col];
                    float4 cw = *(const float4*)&g_ctrl_Wh[bb * DD + col];
                    float4 o;
                    { float cand = sigmoidf_(acc[i][h+0] + cw.x);
                      float w = u*cand + (1.0f-u)*lh.x; o.x = at*w + (1.0f-at)*lh.x; }
                    { float cand = sigmoidf_(acc[i][h+1] + cw.y);
                      float w = u*cand + (1.0f-u)*lh.y; o.y = at*w + (1.0f-at)*lh.y; }
                    { float cand = sigmoidf_(acc[i][h+2] + cw.z);
                      float w = u*cand + (1.0f-u)*lh.z; o.z = at*w + (1.0f-at)*lh.z; }
                    { float cand = sigmoidf_(acc[i][h+3] + cw.w);
                      float w = u*cand + (1.0f-u)*lh.w; o.w = at*w + (1.0f-at)*lh.w; }
                    *(float4*)(crow + h) = o;
                }
            } else {
                #pragma unroll
                for (int h = 0; h < 8; h += 4) {
                    float4 o = make_float4(acc[i][h], acc[i][h+1], acc[i][h+2], acc[i][h+3]);
                    if (MODE == MODE_RELU) {
                        o.x = fmaxf(o.x, 0.0f); o.y = fmaxf(o.y, 0.0f);
                        o.z = fmaxf(o.z, 0.0f); o.w = fmaxf(o.w, 0.0f);
                    }
                    *(float4*)(crow + h) = o;
                }
            }
        }
    }
}

// ---- deterministic split-K reduction (+ optional relu) ----
template<int ACT>
__global__ void reduce_kernel(float* __restrict__ dst, const float* __restrict__ part,
                              int S, int n4)
{
    int i = blockIdx.x * blockDim.x + threadIdx.x;
    if (i >= n4) return;
    const float4* p = (const float4*)part;
    float4 s = p[i];
    for (int k = 1; k < S; k++) {
        float4 v = p[(size_t)k * n4 + i];
        s.x += v.x; s.y += v.y; s.z += v.z; s.w += v.w;
    }
    if (ACT == 1) {
        s.x = fmaxf(s.x, 0.0f); s.y = fmaxf(s.y, 0.0f);
        s.z = fmaxf(s.z, 0.0f); s.w = fmaxf(s.w, 0.0f);
    }
    ((float4*)dst)[i] = s;
}

// ---- per-batch control dot products: ctrl.W_s[512:], ctrl.W_T[512:] ----
__global__ void ctrl_kernel(const float* __restrict__ h0,
                            const float* __restrict__ Ws,
                            const float* __restrict__ WT)
{
    int b = blockIdx.x;
    int lane = threadIdx.x;
    float s1 = 0.0f, s2 = 0.0f;
    for (int u = lane; u < UU; u += 32) {
        float h = h0[b * UU + u];
        s1 += h * Ws[DD + u];
        s2 += h * WT[DD + u];
    }
    #pragma unroll
    for (int o = 16; o; o >>= 1) {
        s1 += __shfl_xor_sync(0xffffffffu, s1, o);
        s2 += __shfl_xor_sync(0xffffffffu, s2, o);
    }
    if (lane == 0) { g_ctrl_s[b] = s1; g_ctrl_T[b] = s2; }
}

// ---- search gates mr for all 255*B internal nodes (warp per node) ----
__global__ void mr_kernel(const float* __restrict__ Ws)
{
    int gw = (blockIdx.x * blockDim.x + threadIdx.x) >> 5;
    int lane = threadIdx.x & 31;
    if (gw >= NROWS_LVL) return;
    const float* row = g_levels + (size_t)gw * DD;
    float s = 0.0f;
    #pragma unroll 4
    for (int k = lane; k < DD; k += 32) s += row[k] * Ws[k];
    #pragma unroll
    for (int o = 16; o; o >>= 1) s += __shfl_xor_sync(0xffffffffu, s, o);
    if (lane == 0) {
        int l = 1;
        #pragma unroll
        for (int i = 2; i <= 8; i++) if (gw >= c_lvl_off[i]) l = i;
        int b = (gw - c_lvl_off[l]) / c_lvl_m[l];
        g_mr[gw] = sigmoidf_(s + g_ctrl_s[b]);
    }
}

// ---- leaf attention: product of 8 path-gate factors ----
__global__ void attn_kernel()
{
    int b = blockIdx.x;
    int leaf = threadIdx.x;
    float a = 1.0f;
    #pragma unroll
    for (int l = 1; l <= 8; l++) {
        int m = NL >> l;
        int j = leaf >> l;
        int c = leaf >> (l - 1);
        float mr = g_mr[c_lvl_off[l] + b * m + j];
        a *= (c & 1) ? mr : (1.0f - mr);
    }
    g_attn[b * NL + leaf] = a;
}

// ---- tree_out[b,e] = sum_n attn[b,n] * inputs[b,n,e] ----
__global__ void treeout_kernel(const float* __restrict__ inputs)
{
    __shared__ float sa[NL];
    int b = blockIdx.x;
    int e = threadIdx.x;
    if (e < NL) sa[e] = g_attn[b * NL + e];
    __syncthreads();
    float s = 0.0f;
    const float* base = inputs + (size_t)b * NL * EE + e;
    #pragma unroll 4
    for (int n = 0; n < NL; n++) s += sa[n] * base[(size_t)n * EE];
    g_tree_out[b * EE + e] = s;
}

// ---- write gate upd per leaf row (warp per row) ----
__global__ void upd_kernel(const float* __restrict__ WT)
{
    int gw = (blockIdx.x * blockDim.x + threadIdx.x) >> 5;
    int lane = threadIdx.x & 31;
    if (gw >= NROWS_LEAF) return;
    const float* row = g_leaf_h + (size_t)gw * DD;
    float s = 0.0f;
    #pragma unroll 4
    for (int k = lane; k < DD; k += 32) s += row[k] * WT[k];
    #pragma unroll
    for (int o = 16; o; o >>= 1) s += __shfl_xor_sync(0xffffffffu, s, o);
    if (lane == 0) g_upd[gw] = sigmoidf_(s + g_ctrl_T[gw >> 8]);
}

// ---- LSTM gates -> h_new, c_new (bias folded in here) ----
__global__ void lstmgate_kernel(const float* __restrict__ c0,
                                const float* __restrict__ bias,
                                float* __restrict__ out_h,
                                float* __restrict__ out_c)
{
    int b = blockIdx.x;
    int u = threadIdx.x;
    float zi = g_z[b * 2048 + u]        + bias[u];
    float zf = g_z[b * 2048 + 512 + u]  + bias[512 + u];
    float zg = g_z[b * 2048 + 1024 + u] + bias[1024 + u];
    float zo = g_z[b * 2048 + 1536 + u] + bias[1536 + u];
    float c = sigmoidf_(zf) * c0[b * UU + u] + sigmoidf_(zi) * tanhf(zg);
    float h = sigmoidf_(zo) * tanhf(c);
    out_h[b * UU + u] = h;
    out_c[b * UU + u] = c;
}

// ============================================================================
extern "C" void kernel_launch(void* const* d_in, const int* in_sizes, int n_in,
                              void* d_out, int out_size)
{
    const float* inputs = (const float*)d_in[0];
    const float* h0     = (const float*)d_in[1];
    const float* c0     = (const float*)d_in[2];
    const float* W_t    = (const float*)d_in[3];
    const float* W_j    = (const float*)d_in[4];
    const float* W_s    = (const float*)d_in[5];
    const float* W_h    = (const float*)d_in[6];
    const float* W_T    = (const float*)d_in[7];
    const float* kern   = (const float*)d_in[8];
    const float* rec    = (const float*)d_in[9];
    const float* bias   = (const float*)d_in[10];

    float* out      = (float*)d_out;
    float* out_h    = out;
    float* out_c    = out + BB * UU;
    float* out_leaf = out + 2 * BB * UU;

    float *p_leaf, *p_levels, *p_part, *p_ctrlWh, *p_z, *p_tree;
    cudaGetSymbolAddress((void**)&p_leaf,   g_leaf_h);
    cudaGetSymbolAddress((void**)&p_levels, g_levels);
    cudaGetSymbolAddress((void**)&p_part,   g_part);
    cudaGetSymbolAddress((void**)&p_ctrlWh, g_ctrl_Wh);
    cudaGetSymbolAddress((void**)&p_z,      g_z);
    cudaGetSymbolAddress((void**)&p_tree,   g_tree_out);

    dim3 blk(256);
    const int lvl_off[10] = {0, 0, 8192, 12288, 14336, 15360, 15872, 16128, 16256, 16320};

    // 1) leaf embed: relu(inputs @ W_t)
    gemm128<MODE_RELU><<<dim3(DD/128, NROWS_LEAF/128, 1), blk>>>(
        p_leaf, inputs, W_t, NROWS_LEAF, DD, EE, EE);

    // 2) join level 1 (M=8192, K=1024): direct relu GEMM
    gemm128<MODE_RELU><<<dim3(DD/128, (BB*(NL>>1))/128, 1), blk>>>(
        p_levels, p_leaf, W_j, BB*(NL>>1), DD, 2*DD, 2*DD);

    // 3) join levels 2..8: deterministic split-K + relu reduce
    //    partial footprint = S * Mrows * 512 floats; max = 8,388,608 (lvl 2 & 3)
    const int splitS[9] = {0, 1, 4, 8, 8, 16, 16, 32, 32};
    const float* src = p_levels;
    for (int l = 2; l <= 8; l++) {
        int Mrows = BB * (NL >> l);
        int S     = splitS[l];
        int chunk = (2*DD) / S;
        float* dst = p_levels + (size_t)lvl_off[l] * DD;
        gemm128<MODE_PART><<<dim3(DD/128, (Mrows + 127)/128, S), blk>>>(
            p_part, src, W_j, Mrows, DD, 2*DD, chunk);
        int n4 = (Mrows * DD) / 4;
        reduce_kernel<1><<<(n4 + 255)/256, 256>>>(dst, p_part, S, n4);
        src = dst;
    }

    // 4) per-batch control terms; ctrl_Wh = h0 @ W_h[512:,:] (split-K S=8)
    ctrl_kernel<<<BB, 32>>>(h0, W_s, W_T);
    gemm128<MODE_PART><<<dim3(DD/128, 1, 8), blk>>>(
        p_part, h0, W_h + DD*DD, BB, DD, UU, UU/8);
    reduce_kernel<0><<<(BB*DD/4 + 255)/256, 256>>>(p_ctrlWh, p_part, 8, BB*DD/4);

    // 5) search gates, attentions, retrieval, write gates
    mr_kernel<<<(NROWS_LVL * 32 + 255)/256, 256>>>(W_s);
    attn_kernel<<<BB, NL>>>();
    treeout_kernel<<<BB, EE>>>(inputs);
    upd_kernel<<<(NROWS_LEAF * 32 + 255)/256, 256>>>(W_T);

    // 6) fused write-update GEMM straight into d_out
    gemm128<MODE_WRITE><<<dim3(DD/128, NROWS_LEAF/128, 1), blk>>>(
        out_leaf, p_leaf, W_h, NROWS_LEAF, DD, DD, DD);

    // 7) LSTM z: tree_out@kernel -> partials 0..7, h0@rec_kernel -> 8..15,
    //    reduce S=16, then gates (+bias).
    gemm128<MODE_PART><<<dim3(4*UU/128, 1, 8), blk>>>(
        p_part, p_tree, kern, BB, 4*UU, EE, EE/8);
    gemm128<MODE_PART><<<dim3(4*UU/128, 1, 8), blk>>>(
        p_part + 8 * BB * 4*UU, h0, rec, BB, 4*UU, UU, UU/8);
    reduce_kernel<0><<<(BB*4*UU/4 + 255)/256, 256>>>(p_z, p_part, 16, BB*4*UU/4);
    lstmgate_kernel<<<BB, UU>>>(c0, bias, out_h, out_c);
}

// round 13
// speedup vs baseline: 2.3016x; 1.7395x over previous
#include <cuda_runtime.h>
#include <cuda_bf16.h>
#include <math.h>
#include <stdint.h>

#define BB 64
#define NL 256
#define EE 512
#define DD 512
#define UU 512

#define NROWS_LEAF (BB*NL)   // 16384
#define NROWS_LVL  16320     // sum over levels 1..8 of B*(256>>l)

// ---- scratch (device globals; no allocation allowed) ----
__device__ float g_leaf_h[NROWS_LEAF*DD];     // 33.5 MB
__device__ float g_levels[NROWS_LVL*DD];      // 33.4 MB, levels 1..8 packed
__device__ float g_part[8388608];             // 32 MB split-K partials (lvl2: 4*4096*512)
__device__ float g_mr[NROWS_LVL];
__device__ float g_ctrl_s[BB];
__device__ float g_ctrl_T[BB];
__device__ float g_ctrl_Wh[BB*DD];
__device__ float g_attn[NROWS_LEAF];
__device__ float g_upd[NROWS_LEAF];
__device__ float g_tree_out[BB*EE];
__device__ float g_z[BB*4*UU];

__constant__ int c_lvl_off[10] = {0, 0, 8192, 12288, 14336, 15360, 15872, 16128, 16256, 16320};
__constant__ int c_lvl_m[9]   = {0, 128, 64, 32, 16, 8, 4, 2, 1};

__device__ __forceinline__ float sigmoidf_(float x) { return 1.0f / (1.0f + expf(-x)); }

#define MODE_RAW   0
#define MODE_RELU  1
#define MODE_WRITE 2
#define MODE_PART  3

// pack fp32 -> (bf16 hi | bf16 lo<<16); hi+lo carries ~16 mantissa bits
__device__ __forceinline__ uint32_t pack_hilo_(float f) {
    __nv_bfloat16 h = __float2bfloat16_rn(f);
    float r = f - __bfloat162float(h);
    __nv_bfloat16 l = __float2bfloat16_rn(r);
    return (uint32_t)__bfloat16_as_ushort(h) | ((uint32_t)__bfloat16_as_ushort(l) << 16);
}

__device__ __forceinline__ void mma_bf16_(float* d, const uint32_t* a, const uint32_t* b) {
    asm volatile(
        "mma.sync.aligned.m16n8k16.row.col.f32.bf16.bf16.f32 "
        "{%0,%1,%2,%3}, {%4,%5,%6,%7}, {%8,%9}, {%0,%1,%2,%3};"
        : "+f"(d[0]), "+f"(d[1]), "+f"(d[2]), "+f"(d[3])
        : "r"(a[0]), "r"(a[1]), "r"(a[2]), "r"(a[3]), "r"(b[0]), "r"(b[1]));
}

// ============================================================================
// bf16x3 (hi/lo split) mma.sync GEMM: C[M,N] = act(A[M,K] @ B[K,N]) over K
// range [z*kChunk, (z+1)*kChunk). Block tile 128x128, BK=16, 256 threads
// (8 warps, warp tile 64x32 = 4 m-frags x 4 n-frags of m16n8k16).
// Effective precision ~fp16-class mantissa (hi*hi + hi*lo + lo*hi), fp32 acc.
// Double-buffered SMEM, register-staged prefetch. N%128==0, kChunk%16==0,
// rows guarded vs M. SMEM word stride 132 -> conflict-free fragment loads
// (addr mod 32 = 8*(lane&3) + (lane>>2)). MODE_PART -> partials at C + z*M*N.
// ============================================================================
template<int MODE>
__global__ void __launch_bounds__(256, 2)
mma_gemm(float* __restrict__ C, const float* __restrict__ A,
         const float* __restrict__ Bmat, int M, int N, int K, int kChunk)
{
    __shared__ __align__(16) uint32_t As[2][16][132];   // transposed: As[k][m], packed hi|lo
    __shared__ __align__(16) uint32_t Bs[2][16][132];   // Bs[k][n], packed hi|lo

    const int tid  = threadIdx.x;
    const int lane = tid & 31;
    const int w    = tid >> 5;
    const int row0 = blockIdx.y * 128;
    const int col0 = blockIdx.x * 128;
    const int wm0  = (w >> 2) * 64;       // warp row offset in tile
    const int wn0  = (w & 3) * 32;        // warp col offset in tile

    // staging assignments
    const int a_row = tid >> 1;           // 0..127
    const int a_k   = (tid & 1) * 8;      // 0 or 8
    const int b_k   = tid >> 4;           // 0..15
    const int b_n   = (tid & 15) * 8;     // 0..120

    const int  kBeg  = blockIdx.z * kChunk;
    const int  nIter = kChunk >> 4;
    const bool a_ok  = (row0 + a_row) < M;

    const float* Aptr = A + (size_t)(row0 + a_row) * K + kBeg + a_k;
    const float* Bptr = Bmat + (size_t)(kBeg + b_k) * N + col0 + b_n;

    float acc[4][4][4];
    #pragma unroll
    for (int i = 0; i < 4; i++)
        #pragma unroll
        for (int j = 0; j < 4; j++)
            #pragma unroll
            for (int h = 0; h < 4; h++) acc[i][j][h] = 0.0f;

    uint32_t a_st[8], b_st[8];

    // ---- prologue: stage 0 ----
    {
        float4 v0 = make_float4(0,0,0,0), v1 = v0;
        if (a_ok) { v0 = *(const float4*)(Aptr); v1 = *(const float4*)(Aptr + 4); }
        a_st[0]=pack_hilo_(v0.x); a_st[1]=pack_hilo_(v0.y); a_st[2]=pack_hilo_(v0.z); a_st[3]=pack_hilo_(v0.w);
        a_st[4]=pack_hilo_(v1.x); a_st[5]=pack_hilo_(v1.y); a_st[6]=pack_hilo_(v1.z); a_st[7]=pack_hilo_(v1.w);
        float4 w0 = *(const float4*)(Bptr);
        float4 w1 = *(const float4*)(Bptr + 4);
        b_st[0]=pack_hilo_(w0.x); b_st[1]=pack_hilo_(w0.y); b_st[2]=pack_hilo_(w0.z); b_st[3]=pack_hilo_(w0.w);
        b_st[4]=pack_hilo_(w1.x); b_st[5]=pack_hilo_(w1.y); b_st[6]=pack_hilo_(w1.z); b_st[7]=pack_hilo_(w1.w);
    }
    #pragma unroll
    for (int i = 0; i < 8; i++) As[0][a_k + i][a_row] = a_st[i];
    *(uint4*)&Bs[0][b_k][b_n]     = make_uint4(b_st[0], b_st[1], b_st[2], b_st[3]);
    *(uint4*)&Bs[0][b_k][b_n + 4] = make_uint4(b_st[4], b_st[5], b_st[6], b_st[7]);
    __syncthreads();

    int buf = 0;
    for (int t = 0; t < nIter; t++) {
        if (t + 1 < nIter) {
            float4 v0 = make_float4(0,0,0,0), v1 = v0;
            if (a_ok) { v0 = *(const float4*)(Aptr + (t+1)*16);
                        v1 = *(const float4*)(Aptr + (t+1)*16 + 4); }
            a_st[0]=pack_hilo_(v0.x); a_st[1]=pack_hilo_(v0.y); a_st[2]=pack_hilo_(v0.z); a_st[3]=pack_hilo_(v0.w);
            a_st[4]=pack_hilo_(v1.x); a_st[5]=pack_hilo_(v1.y); a_st[6]=pack_hilo_(v1.z); a_st[7]=pack_hilo_(v1.w);
            float4 w0 = *(const float4*)(Bptr + (size_t)(t+1)*16*N);
            float4 w1 = *(const float4*)(Bptr + (size_t)(t+1)*16*N + 4);
            b_st[0]=pack_hilo_(w0.x); b_st[1]=pack_hilo_(w0.y); b_st[2]=pack_hilo_(w0.z); b_st[3]=pack_hilo_(w0.w);
            b_st[4]=pack_hilo_(w1.x); b_st[5]=pack_hilo_(w1.y); b_st[6]=pack_hilo_(w1.z); b_st[7]=pack_hilo_(w1.w);
        }

        // ---- compute on current buffer: one m16n8k16 step, 3 passes ----
        {
            const int t4 = lane & 3;           // thread-in-group
            const int g  = lane >> 2;          // group id
            uint32_t ah[4][4], al[4][4];
            #pragma unroll
            for (int mf = 0; mf < 4; mf++) {
                const int m0 = wm0 + mf*16 + g;
                #pragma unroll
                for (int q = 0; q < 4; q++) {
                    // q: 0 -> a0 (k lo, row g), 1 -> a1 (k lo, row g+8),
                    //    2 -> a2 (k hi, row g), 3 -> a3 (k hi, row g+8)
                    const int kq = 2*t4 + (q >> 1)*8;
                    const int mq = m0 + (q & 1)*8;
                    uint32_t w0 = As[buf][kq    ][mq];
                    uint32_t w1 = As[buf][kq + 1][mq];
                    ah[mf][q] = __byte_perm(w0, w1, 0x5410);
                    al[mf][q] = __byte_perm(w0, w1, 0x7632);
                }
            }
            #pragma unroll
            for (int nf = 0; nf < 4; nf++) {
                const int n0 = wn0 + nf*8 + g;
                uint32_t bh[2], bl[2];
                #pragma unroll
                for (int q = 0; q < 2; q++) {
                    const int kq = 2*t4 + q*8;
                    uint32_t w0 = Bs[buf][kq    ][n0];
                    uint32_t w1 = Bs[buf][kq + 1][n0];
                    bh[q] = __byte_perm(w0, w1, 0x5410);
                    bl[q] = __byte_perm(w0, w1, 0x7632);
                }
                #pragma unroll
                for (int mf = 0; mf < 4; mf++) {
                    mma_bf16_(acc[mf][nf], ah[mf], bh);   // hi*hi
                    mma_bf16_(acc[mf][nf], ah[mf], bl);   // hi*lo
                    mma_bf16_(acc[mf][nf], al[mf], bh);   // lo*hi
                }
            }
        }

        if (t + 1 < nIter) {
            #pragma unroll
            for (int i = 0; i < 8; i++) As[buf^1][a_k + i][a_row] = a_st[i];
            *(uint4*)&Bs[buf^1][b_k][b_n]     = make_uint4(b_st[0], b_st[1], b_st[2], b_st[3]);
            *(uint4*)&Bs[buf^1][b_k][b_n + 4] = make_uint4(b_st[4], b_st[5], b_st[6], b_st[7]);
        }
        __syncthreads();
        buf ^= 1;
    }

    // ---- epilogue ----
    // fragment C: c0,c1 -> (row = lane>>2, col = 2*(lane&3)+{0,1}); c2,c3 -> row+8
    float* Cbase = C;
    if (MODE == MODE_PART) Cbase = C + (size_t)blockIdx.z * M * N;

    #pragma unroll
    for (int mf = 0; mf < 4; mf++) {
        const int rbase = row0 + wm0 + mf*16 + (lane >> 2);
        #pragma unroll
        for (int half = 0; half < 2; half++) {
            const int r = rbase + half * 8;
            if (r < M) {
                const int cb = col0 + wn0 + (lane & 3) * 2;
                float* crow = Cbase + (size_t)r * N + cb;
                float u = 0.f, at = 0.f; int bb = 0;
                if (MODE == MODE_WRITE) { u = g_upd[r]; at = g_attn[r]; bb = r >> 8; }
                #pragma unroll
                for (int nf = 0; nf < 4; nf++) {
                    float d0 = acc[mf][nf][half*2 + 0];
                    float d1 = acc[mf][nf][half*2 + 1];
                    if (MODE == MODE_RELU) {
                        d0 = fmaxf(d0, 0.f); d1 = fmaxf(d1, 0.f);
                    } else if (MODE == MODE_WRITE) {
                        const int col = cb + nf*8;
                        float2 lh = *(const float2*)&g_leaf_h[(size_t)r * DD + col];
                        float2 cw = *(const float2*)&g_ctrl_Wh[bb * DD + col];
                        { float cd = sigmoidf_(d0 + cw.x);
                          float wv = u*cd + (1.f-u)*lh.x; d0 = at*wv + (1.f-at)*lh.x; }
                        { float cd = sigmoidf_(d1 + cw.y);
                          float wv = u*cd + (1.f-u)*lh.y; d1 = at*wv + (1.f-at)*lh.y; }
                    }
                    *(float2*)(crow + nf*8) = make_float2(d0, d1);
                }
            }
        }
    }
}

// ============================================================================
// fp32 split-K GEMM (exact; for M=64 GEMMs: ctrl_Wh, LSTM z)
// ============================================================================
template<int MODE>
__global__ void __launch_bounds__(256, 2)
gemm128(float* __restrict__ C, const float* __restrict__ A,
        const float* __restrict__ Bmat, int M, int N, int K, int kChunk)
{
    __shared__ float As[2][16][136];
    __shared__ float Bs[2][16][128];

    const int tid  = threadIdx.x;
    const int row0 = blockIdx.y * 128;
    const int col0 = blockIdx.x * 128;
    const int ty = tid >> 4;
    const int tx = tid & 15;
    const int a_r = tid >> 1;
    const int a_k = (tid & 1) * 8;
    const int b_k = tid >> 4;
    const int b_n = (tid & 15) * 8;

    const int  kBeg  = blockIdx.z * kChunk;
    const int  nIter = kChunk >> 4;
    const bool a_ok  = (row0 + a_r) < M;

    const float* Aptr = A + (size_t)(row0 + a_r) * K + kBeg + a_k;
    const float* Bptr = Bmat + (size_t)(kBeg + b_k) * N + col0 + b_n;

    float acc[8][8];
    #pragma unroll
    for (int i = 0; i < 8; i++)
        #pragma unroll
        for (int j = 0; j < 8; j++) acc[i][j] = 0.0f;

    float a_st[8], b_st[8];
    {
        float4 v0 = make_float4(0,0,0,0), v1 = v0;
        if (a_ok) { v0 = *(const float4*)(Aptr); v1 = *(const float4*)(Aptr + 4); }
        a_st[0]=v0.x; a_st[1]=v0.y; a_st[2]=v0.z; a_st[3]=v0.w;
        a_st[4]=v1.x; a_st[5]=v1.y; a_st[6]=v1.z; a_st[7]=v1.w;
        float4 w0 = *(const float4*)(Bptr);
        float4 w1 = *(const float4*)(Bptr + 4);
        b_st[0]=w0.x; b_st[1]=w0.y; b_st[2]=w0.z; b_st[3]=w0.w;
        b_st[4]=w1.x; b_st[5]=w1.y; b_st[6]=w1.z; b_st[7]=w1.w;
    }
    #pragma unroll
    for (int i = 0; i < 8; i++) As[0][a_k + i][a_r] = a_st[i];
    *(float4*)&Bs[0][b_k][b_n]     = make_float4(b_st[0], b_st[1], b_st[2], b_st[3]);
    *(float4*)&Bs[0][b_k][b_n + 4] = make_float4(b_st[4], b_st[5], b_st[6], b_st[7]);
    __syncthreads();

    int buf = 0;
    for (int t = 0; t < nIter; t++) {
        if (t + 1 < nIter) {
            float4 v0 = make_float4(0,0,0,0), v1 = v0;
            if (a_ok) { v0 = *(const float4*)(Aptr + (t+1)*16);
                        v1 = *(const float4*)(Aptr + (t+1)*16 + 4); }
            a_st[0]=v0.x; a_st[1]=v0.y; a_st[2]=v0.z; a_st[3]=v0.w;
            a_st[4]=v1.x; a_st[5]=v1.y; a_st[6]=v1.z; a_st[7]=v1.w;
            float4 w0 = *(const float4*)(Bptr + (size_t)(t+1)*16*N);
            float4 w1 = *(const float4*)(Bptr + (size_t)(t+1)*16*N + 4);
            b_st[0]=w0.x; b_st[1]=w0.y; b_st[2]=w0.z; b_st[3]=w0.w;
            b_st[4]=w1.x; b_st[5]=w1.y; b_st[6]=w1.z; b_st[7]=w1.w;
        }
        #pragma unroll
        for (int kk = 0; kk < 16; kk++) {
            float a[8], b[8];
            *(float4*)(a)     = *(const float4*)&As[buf][kk][ty*8];
            *(float4*)(a + 4) = *(const float4*)&As[buf][kk][ty*8 + 4];
            *(float4*)(b)     = *(const float4*)&Bs[buf][kk][tx*8];
            *(float4*)(b + 4) = *(const float4*)&Bs[buf][kk][tx*8 + 4];
            #pragma unroll
            for (int i = 0; i < 8; i++)
                #pragma unroll
                for (int j = 0; j < 8; j++)
                    acc[i][j] = fmaf(a[i], b[j], acc[i][j]);
        }
        if (t + 1 < nIter) {
            #pragma unroll
            for (int i = 0; i < 8; i++) As[buf^1][a_k + i][a_r] = a_st[i];
            *(float4*)&Bs[buf^1][b_k][b_n]     = make_float4(b_st[0], b_st[1], b_st[2], b_st[3]);
            *(float4*)&Bs[buf^1][b_k][b_n + 4] = make_float4(b_st[4], b_st[5], b_st[6], b_st[7]);
        }
        __syncthreads();
        buf ^= 1;
    }

    float* Cbase = C;
    if (MODE == MODE_PART) Cbase = C + (size_t)blockIdx.z * M * N;

    #pragma unroll
    for (int i = 0; i < 8; i++) {
        int r = row0 + ty*8 + i;
        if (r < M) {
            float* crow = Cbase + (size_t)r * N + col0 + tx*8;
            #pragma unroll
            for (int h = 0; h < 8; h += 4) {
                float4 o = make_float4(acc[i][h], acc[i][h+1], acc[i][h+2], acc[i][h+3]);
                if (MODE == MODE_RELU) {
                    o.x = fmaxf(o.x, 0.0f); o.y = fmaxf(o.y, 0.0f);
                    o.z = fmaxf(o.z, 0.0f); o.w = fmaxf(o.w, 0.0f);
                }
                *(float4*)(crow + h) = o;
            }
        }
    }
}

// ---- deterministic split-K reduction (+ optional relu) ----
template<int ACT>
__global__ void reduce_kernel(float* __restrict__ dst, const float* __restrict__ part,
                              int S, int n4)
{
    int i = blockIdx.x * blockDim.x + threadIdx.x;
    if (i >= n4) return;
    const float4* p = (const float4*)part;
    float4 s = p[i];
    for (int k = 1; k < S; k++) {
        float4 v = p[(size_t)k * n4 + i];
        s.x += v.x; s.y += v.y; s.z += v.z; s.w += v.w;
    }
    if (ACT == 1) {
        s.x = fmaxf(s.x, 0.0f); s.y = fmaxf(s.y, 0.0f);
        s.z = fmaxf(s.z, 0.0f); s.w = fmaxf(s.w, 0.0f);
    }
    ((float4*)dst)[i] = s;
}

// ---- per-batch control dot products: ctrl.W_s[512:], ctrl.W_T[512:] ----
__global__ void ctrl_kernel(const float* __restrict__ h0,
                            const float* __restrict__ Ws,
                            const float* __restrict__ WT)
{
    int b = blockIdx.x;
    int lane = threadIdx.x;
    float s1 = 0.0f, s2 = 0.0f;
    for (int u = lane; u < UU; u += 32) {
        float h = h0[b * UU + u];
        s1 += h * Ws[DD + u];
        s2 += h * WT[DD + u];
    }
    #pragma unroll
    for (int o = 16; o; o >>= 1) {
        s1 += __shfl_xor_sync(0xffffffffu, s1, o);
        s2 += __shfl_xor_sync(0xffffffffu, s2, o);
    }
    if (lane == 0) { g_ctrl_s[b] = s1; g_ctrl_T[b] = s2; }
}

// ---- search gates mr for all 255*B internal nodes (warp per node) ----
__global__ void mr_kernel(const float* __restrict__ Ws)
{
    int gw = (blockIdx.x * blockDim.x + threadIdx.x) >> 5;
    int lane = threadIdx.x & 31;
    if (gw >= NROWS_LVL) return;
    const float* row = g_levels + (size_t)gw * DD;
    float s = 0.0f;
    #pragma unroll 4
    for (int k = lane; k < DD; k += 32) s += row[k] * Ws[k];
    #pragma unroll
    for (int o = 16; o; o >>= 1) s += __shfl_xor_sync(0xffffffffu, s, o);
    if (lane == 0) {
        int l = 1;
        #pragma unroll
        for (int i = 2; i <= 8; i++) if (gw >= c_lvl_off[i]) l = i;
        int b = (gw - c_lvl_off[l]) / c_lvl_m[l];
        g_mr[gw] = sigmoidf_(s + g_ctrl_s[b]);
    }
}

// ---- leaf attention: product of 8 path-gate factors ----
__global__ void attn_kernel()
{
    int b = blockIdx.x;
    int leaf = threadIdx.x;
    float a = 1.0f;
    #pragma unroll
    for (int l = 1; l <= 8; l++) {
        int m = NL >> l;
        int j = leaf >> l;
        int c = leaf >> (l - 1);
        float mr = g_mr[c_lvl_off[l] + b * m + j];
        a *= (c & 1) ? mr : (1.0f - mr);
    }
    g_attn[b * NL + leaf] = a;
}

// ---- tree_out[b,e] = sum_n attn[b,n] * inputs[b,n,e] ----
__global__ void treeout_kernel(const float* __restrict__ inputs)
{
    __shared__ float sa[NL];
    int b = blockIdx.x;
    int e = threadIdx.x;
    if (e < NL) sa[e] = g_attn[b * NL + e];
    __syncthreads();
    float s = 0.0f;
    const float* base = inputs + (size_t)b * NL * EE + e;
    #pragma unroll 4
    for (int n = 0; n < NL; n++) s += sa[n] * base[(size_t)n * EE];
    g_tree_out[b * EE + e] = s;
}

// ---- write gate upd per leaf row (warp per row) ----
__global__ void upd_kernel(const float* __restrict__ WT)
{
    int gw = (blockIdx.x * blockDim.x + threadIdx.x) >> 5;
    int lane = threadIdx.x & 31;
    if (gw >= NROWS_LEAF) return;
    const float* row = g_leaf_h + (size_t)gw * DD;
    float s = 0.0f;
    #pragma unroll 4
    for (int k = lane; k < DD; k += 32) s += row[k] * WT[k];
    #pragma unroll
    for (int o = 16; o; o >>= 1) s += __shfl_xor_sync(0xffffffffu, s, o);
    if (lane == 0) g_upd[gw] = sigmoidf_(s + g_ctrl_T[gw >> 8]);
}

// ---- LSTM gates -> h_new, c_new (bias folded in here) ----
__global__ void lstmgate_kernel(const float* __restrict__ c0,
                                const float* __restrict__ bias,
                                float* __restrict__ out_h,
                                float* __restrict__ out_c)
{
    int b = blockIdx.x;
    int u = threadIdx.x;
    float zi = g_z[b * 2048 + u]        + bias[u];
    float zf = g_z[b * 2048 + 512 + u]  + bias[512 + u];
    float zg = g_z[b * 2048 + 1024 + u] + bias[1024 + u];
    float zo = g_z[b * 2048 + 1536 + u] + bias[1536 + u];
    float c = sigmoidf_(zf) * c0[b * UU + u] + sigmoidf_(zi) * tanhf(zg);
    float h = sigmoidf_(zo) * tanhf(c);
    out_h[b * UU + u] = h;
    out_c[b * UU + u] = c;
}

// ============================================================================
extern "C" void kernel_launch(void* const* d_in, const int* in_sizes, int n_in,
                              void* d_out, int out_size)
{
    const float* inputs = (const float*)d_in[0];
    const float* h0     = (const float*)d_in[1];
    const float* c0     = (const float*)d_in[2];
    const float* W_t    = (const float*)d_in[3];
    const float* W_j    = (const float*)d_in[4];
    const float* W_s    = (const float*)d_in[5];
    const float* W_h    = (const float*)d_in[6];
    const float* W_T    = (const float*)d_in[7];
    const float* kern   = (const float*)d_in[8];
    const float* rec    = (const float*)d_in[9];
    const float* bias   = (const float*)d_in[10];

    float* out      = (float*)d_out;
    float* out_h    = out;
    float* out_c    = out + BB * UU;
    float* out_leaf = out + 2 * BB * UU;

    float *p_leaf, *p_levels, *p_part, *p_ctrlWh, *p_z, *p_tree;
    cudaGetSymbolAddress((void**)&p_leaf,   g_leaf_h);
    cudaGetSymbolAddress((void**)&p_levels, g_levels);
    cudaGetSymbolAddress((void**)&p_part,   g_part);
    cudaGetSymbolAddress((void**)&p_ctrlWh, g_ctrl_Wh);
    cudaGetSymbolAddress((void**)&p_z,      g_z);
    cudaGetSymbolAddress((void**)&p_tree,   g_tree_out);

    dim3 blk(256);
    const int lvl_off[10] = {0, 0, 8192, 12288, 14336, 15360, 15872, 16128, 16256, 16320};

    // 1) leaf embed: relu(inputs @ W_t)  [16384,512]x[512,512]  (bf16x3 mma)
    mma_gemm<MODE_RELU><<<dim3(DD/128, NROWS_LEAF/128, 1), blk>>>(
        p_leaf, inputs, W_t, NROWS_LEAF, DD, EE, EE);

    // 2) join level 1 (M=8192, K=1024): direct relu GEMM (bf16x3 mma)
    mma_gemm<MODE_RELU><<<dim3(DD/128, (BB*(NL>>1))/128, 1), blk>>>(
        p_levels, p_leaf, W_j, BB*(NL>>1), DD, 2*DD, 2*DD);

    // 3) join levels 2..8: split-K bf16x3 mma + deterministic relu reduce
    //    partial footprint = S * Mrows * 512 floats; max = 8,388,608 (lvl 2 & 3)
    const int splitS[9] = {0, 1, 4, 8, 8, 16, 16, 32, 32};
    const float* src = p_levels;
    for (int l = 2; l <= 8; l++) {
        int Mrows = BB * (NL >> l);
        int S     = splitS[l];
        int chunk = (2*DD) / S;
        float* dst = p_levels + (size_t)lvl_off[l] * DD;
        mma_gemm<MODE_PART><<<dim3(DD/128, (Mrows + 127)/128, S), blk>>>(
            p_part, src, W_j, Mrows, DD, 2*DD, chunk);
        int n4 = (Mrows * DD) / 4;
        reduce_kernel<1><<<(n4 + 255)/256, 256>>>(dst, p_part, S, n4);
        src = dst;
    }

    // 4) per-batch control terms; ctrl_Wh = h0 @ W_h[512:,:] (EXACT fp32 split-K)
    ctrl_kernel<<<BB, 32>>>(h0, W_s, W_T);
    gemm128<MODE_PART><<<dim3(DD/128, 1, 8), blk>>>(
        p_part, h0, W_h + DD*DD, BB, DD, UU, UU/8);
    reduce_kernel<0><<<(BB*DD/4 + 255)/256, 256>>>(p_ctrlWh, p_part, 8, BB*DD/4);

    // 5) search gates, attentions, retrieval, write gates
    mr_kernel<<<(NROWS_LVL * 32 + 255)/256, 256>>>(W_s);
    attn_kernel<<<BB, NL>>>();
    treeout_kernel<<<BB, EE>>>(inputs);
    upd_kernel<<<(NROWS_LEAF * 32 + 255)/256, 256>>>(W_T);

    // 6) fused write-update GEMM straight into d_out (bf16x3 mma)
    mma_gemm<MODE_WRITE><<<dim3(DD/128, NROWS_LEAF/128, 1), blk>>>(
        out_leaf, p_leaf, W_h, NROWS_LEAF, DD, DD, DD);

    // 7) LSTM z (EXACT fp32 split-K): tree_out@kernel -> parts 0..7,
    //    h0@rec_kernel -> parts 8..15, reduce S=16, then gates (+bias)
    gemm128<MODE_PART><<<dim3(4*UU/128, 1, 8), blk>>>(
        p_part, p_tree, kern, BB, 4*UU, EE, EE/8);
    gemm128<MODE_PART><<<dim3(4*UU/128, 1, 8), blk>>>(
        p_part + (size_t)8 * BB * 4*UU, h0, rec, BB, 4*UU, UU, UU/8);
    reduce_kernel<0><<<(BB*4*UU/4 + 255)/256, 256>>>(p_z, p_part, 16, BB*4*UU/4);
    lstmgate_kernel<<<BB, UU>>>(c0, bias, out_h, out_c);
}

// round 14
// speedup vs baseline: 2.7690x; 1.2031x over previous
#include <cuda_runtime.h>
#include <cuda_bf16.h>
#include <math.h>
#include <stdint.h>

#define BB 64
#define NL 256
#define EE 512
#define DD 512
#define UU 512

#define NROWS_LEAF (BB*NL)   // 16384
#define NROWS_LVL  16320     // sum over levels 1..8 of B*(256>>l)

// ---- scratch (device globals; no allocation allowed) ----
__device__ float g_leaf_h[NROWS_LEAF*DD];     // 33.5 MB
__device__ float g_levels[NROWS_LVL*DD];      // 33.4 MB, levels 1..8 packed
__device__ float g_part[8388608];             // 32 MB split-K partials
__device__ float g_mr[NROWS_LVL];
__device__ float g_ctrl_s[BB];
__device__ float g_ctrl_T[BB];
__device__ float g_ctrl_Wh[BB*DD];
__device__ float g_attn[NROWS_LEAF];
__device__ float g_upd[NROWS_LEAF];
__device__ float g_tree_out[BB*EE];
__device__ float g_z[BB*4*UU];

// pre-converted weights, [n][k] layout, hi/lo bf16 planes
__device__ __nv_bfloat16 g_wt_h[512*512],  g_wt_l[512*512];    // W_t^T
__device__ __nv_bfloat16 g_wj_h[512*1024], g_wj_l[512*1024];   // W_j^T
__device__ __nv_bfloat16 g_wh_h[512*512],  g_wh_l[512*512];    // W_h[0:512]^T

__constant__ int c_lvl_off[10] = {0, 0, 8192, 12288, 14336, 15360, 15872, 16128, 16256, 16320};
__constant__ int c_lvl_m[9]   = {0, 128, 64, 32, 16, 8, 4, 2, 1};

__device__ __forceinline__ float sigmoidf_(float x) { return 1.0f / (1.0f + expf(-x)); }

#define MODE_RAW   0
#define MODE_RELU  1
#define MODE_WRITE 2
#define MODE_PART  3

__device__ __forceinline__ void mma_bf16_(float* d, const uint32_t* a, const uint32_t* b) {
    asm volatile(
        "mma.sync.aligned.m16n8k16.row.col.f32.bf16.bf16.f32 "
        "{%0,%1,%2,%3}, {%4,%5,%6,%7}, {%8,%9}, {%0,%1,%2,%3};"
        : "+f"(d[0]), "+f"(d[1]), "+f"(d[2]), "+f"(d[3])
        : "r"(a[0]), "r"(a[1]), "r"(a[2]), "r"(a[3]), "r"(b[0]), "r"(b[1]));
}
__device__ __forceinline__ void ldsm4_(uint32_t* r, uint32_t saddr) {
    asm volatile("ldmatrix.sync.aligned.m8n8.x4.shared.b16 {%0,%1,%2,%3}, [%4];"
        : "=r"(r[0]), "=r"(r[1]), "=r"(r[2]), "=r"(r[3]) : "r"(saddr));
}
// hi pair: truncated bf16 of two floats packed into one word (1 PRMT)
__device__ __forceinline__ uint32_t hipair_(float a, float b) {
    return __byte_perm(__float_as_uint(a), __float_as_uint(b), 0x7632);
}
// lo pair: bf16_rn of residuals after truncation
__device__ __forceinline__ uint32_t lopair_(float a, float b) {
    float ra = a - __uint_as_float(__float_as_uint(a) & 0xffff0000u);
    float rb = b - __uint_as_float(__float_as_uint(b) & 0xffff0000u);
    uint32_t ua = (uint32_t)__bfloat16_as_ushort(__float2bfloat16_rn(ra));
    uint32_t ub = (uint32_t)__bfloat16_as_ushort(__float2bfloat16_rn(rb));
    return ua | (ub << 16);
}

// ============================================================================
// weight pre-convert: W[k][n] fp32 -> oh/ol [n][k] bf16 hi/lo (rn split)
// 32x32 tile transpose, 32x8 threads
// ============================================================================
__global__ void wconv_kernel(const float* __restrict__ W,
                             __nv_bfloat16* __restrict__ oh,
                             __nv_bfloat16* __restrict__ ol,
                             int K, int Nn)
{
    __shared__ float t[32][33];
    int k0 = blockIdx.y * 32, n0 = blockIdx.x * 32;
    int tx = threadIdx.x, ty = threadIdx.y;
    #pragma unroll
    for (int j = 0; j < 4; j++)
        t[ty + j*8][tx] = W[(size_t)(k0 + ty + j*8) * Nn + n0 + tx];
    __syncthreads();
    #pragma unroll
    for (int j = 0; j < 4; j++) {
        float v = t[tx][ty + j*8];                 // = W[k0+tx][n0+ty+j*8]
        __nv_bfloat16 h = __float2bfloat16_rn(v);
        __nv_bfloat16 l = __float2bfloat16_rn(v - __bfloat162float(h));
        size_t o = (size_t)(n0 + ty + j*8) * K + k0 + tx;
        oh[o] = h; ol[o] = l;
    }
}

// ============================================================================
// bf16x3 ldmatrix GEMM: C[M,N] = act(A[M,K] @ B[K,N]) over K range
// [z*kChunk, (z+1)*kChunk). A fp32 [m][k]; B pre-split bf16 [n][k] hi/lo.
// Block tile 128x128, BK=16, 256 threads (8 warps, warp 64x32).
// SMEM: bf16 rows of 16 elems, 48B stride (16B pad) -> ldmatrix conflict-free.
// MODE_PART -> partials at C + z*M*N. Rows guarded vs M; N%128==0.
// ============================================================================
template<int MODE>
__global__ void __launch_bounds__(256, 2)
mma_gemm2(float* __restrict__ C, const float* __restrict__ A,
          const __nv_bfloat16* __restrict__ Bh, const __nv_bfloat16* __restrict__ Bl,
          int M, int N, int K, int kChunk)
{
    // [2 buf][128 rows][12 words] ; row = 16 bf16 (24B... 12 words=48B: 16 data+16 pad)
    __shared__ uint32_t Ah [2][128][12];
    __shared__ uint32_t Alo[2][128][12];
    __shared__ uint32_t Bhs[2][128][12];
    __shared__ uint32_t Bls[2][128][12];

    const int tid  = threadIdx.x;
    const int lane = tid & 31;
    const int w    = tid >> 5;
    const int row0 = blockIdx.y * 128;
    const int col0 = blockIdx.x * 128;
    const int wm0  = (w >> 2) * 64;
    const int wn0  = (w & 3) * 32;

    const int s_row = tid >> 1;          // staging row 0..127
    const int s_kh  = tid & 1;           // k-half 0/1

    const int  kBeg  = blockIdx.z * kChunk;
    const int  nIter = kChunk >> 4;
    const bool a_ok  = (row0 + s_row) < M;

    const float*         Ap  = A  + (size_t)(row0 + s_row) * K + kBeg + s_kh * 8;
    const __nv_bfloat16* Bhp = Bh + (size_t)(col0 + s_row) * K + kBeg + s_kh * 8;
    const __nv_bfloat16* Blp = Bl + (size_t)(col0 + s_row) * K + kBeg + s_kh * 8;

    const uint32_t ahB = (uint32_t)__cvta_generic_to_shared(&Ah [0][0][0]);
    const uint32_t alB = (uint32_t)__cvta_generic_to_shared(&Alo[0][0][0]);
    const uint32_t bhB = (uint32_t)__cvta_generic_to_shared(&Bhs[0][0][0]);
    const uint32_t blB = (uint32_t)__cvta_generic_to_shared(&Bls[0][0][0]);

    float acc[4][4][4];
    #pragma unroll
    for (int i = 0; i < 4; i++)
        #pragma unroll
        for (int j = 0; j < 4; j++)
            #pragma unroll
            for (int h = 0; h < 4; h++) acc[i][j][h] = 0.0f;

    // prologue: load + stage 0
    float4 av0 = make_float4(0,0,0,0), av1 = av0;
    uint4  bh4, bl4;
    if (a_ok) { av0 = *(const float4*)Ap; av1 = *(const float4*)(Ap + 4); }
    bh4 = *(const uint4*)Bhp;
    bl4 = *(const uint4*)Blp;
    {
        uint4 h = make_uint4(hipair_(av0.x,av0.y), hipair_(av0.z,av0.w),
                             hipair_(av1.x,av1.y), hipair_(av1.z,av1.w));
        uint4 l = make_uint4(lopair_(av0.x,av0.y), lopair_(av0.z,av0.w),
                             lopair_(av1.x,av1.y), lopair_(av1.z,av1.w));
        *(uint4*)&Ah [0][s_row][s_kh*4] = h;
        *(uint4*)&Alo[0][s_row][s_kh*4] = l;
        *(uint4*)&Bhs[0][s_row][s_kh*4] = bh4;
        *(uint4*)&Bls[0][s_row][s_kh*4] = bl4;
    }
    __syncthreads();

    // per-lane ldmatrix address offsets (within a buffer)
    const uint32_t aOff = (uint32_t)(wm0 + (lane & 15)) * 48 + ((lane >> 4) * 16);
    const uint32_t bOff = (uint32_t)(wn0 + (lane & 7) + ((lane >> 4) & 1) * 8) * 48
                        + (((lane >> 3) & 1) * 16);

    int buf = 0;
    for (int t = 0; t < nIter; t++) {
        // prefetch next chunk
        if (t + 1 < nIter) {
            av0 = make_float4(0,0,0,0); av1 = av0;
            if (a_ok) { av0 = *(const float4*)(Ap + (t+1)*16);
                        av1 = *(const float4*)(Ap + (t+1)*16 + 4); }
            bh4 = *(const uint4*)(Bhp + (t+1)*16);
            bl4 = *(const uint4*)(Blp + (t+1)*16);
        }

        // ---- fragments via ldmatrix ----
        const uint32_t bufB = (uint32_t)buf * 6144;   // 128*48
        uint32_t ah[4][4], al[4][4];
        #pragma unroll
        for (int mf = 0; mf < 4; mf++) {
            ldsm4_(ah[mf], ahB + bufB + aOff + mf*768);   // 16 rows * 48B
            ldsm4_(al[mf], alB + bufB + aOff + mf*768);
        }
        #pragma unroll
        for (int p = 0; p < 2; p++) {
            uint32_t bhr[4], blr[4];
            ldsm4_(bhr, bhB + bufB + bOff + p*768);
            ldsm4_(blr, blB + bufB + bOff + p*768);
            #pragma unroll
            for (int sub = 0; sub < 2; sub++) {
                const int nf = p*2 + sub;
                uint32_t* bhp = &bhr[sub*2];
                uint32_t* blp = &blr[sub*2];
                #pragma unroll
                for (int mf = 0; mf < 4; mf++) {
                    mma_bf16_(acc[mf][nf], ah[mf], bhp);   // hi*hi
                    mma_bf16_(acc[mf][nf], ah[mf], blp);   // hi*lo
                    mma_bf16_(acc[mf][nf], al[mf], bhp);   // lo*hi
                }
            }
        }

        // commit next stage
        if (t + 1 < nIter) {
            uint4 h = make_uint4(hipair_(av0.x,av0.y), hipair_(av0.z,av0.w),
                                 hipair_(av1.x,av1.y), hipair_(av1.z,av1.w));
            uint4 l = make_uint4(lopair_(av0.x,av0.y), lopair_(av0.z,av0.w),
                                 lopair_(av1.x,av1.y), lopair_(av1.z,av1.w));
            *(uint4*)&Ah [buf^1][s_row][s_kh*4] = h;
            *(uint4*)&Alo[buf^1][s_row][s_kh*4] = l;
            *(uint4*)&Bhs[buf^1][s_row][s_kh*4] = bh4;
            *(uint4*)&Bls[buf^1][s_row][s_kh*4] = bl4;
        }
        __syncthreads();
        buf ^= 1;
    }

    // ---- epilogue ----
    // fragment C: c0,c1 -> (row = lane>>2, col = 2*(lane&3)+{0,1}); c2,c3 -> row+8
    float* Cbase = C;
    if (MODE == MODE_PART) Cbase = C + (size_t)blockIdx.z * M * N;

    #pragma unroll
    for (int mf = 0; mf < 4; mf++) {
        const int rbase = row0 + wm0 + mf*16 + (lane >> 2);
        #pragma unroll
        for (int half = 0; half < 2; half++) {
            const int r = rbase + half * 8;
            if (r < M) {
                const int cb = col0 + wn0 + (lane & 3) * 2;
                float* crow = Cbase + (size_t)r * N + cb;
                float u = 0.f, at = 0.f; int bb = 0;
                if (MODE == MODE_WRITE) { u = g_upd[r]; at = g_attn[r]; bb = r >> 8; }
                #pragma unroll
                for (int nf = 0; nf < 4; nf++) {
                    float d0 = acc[mf][nf][half*2 + 0];
                    float d1 = acc[mf][nf][half*2 + 1];
                    if (MODE == MODE_RELU) {
                        d0 = fmaxf(d0, 0.f); d1 = fmaxf(d1, 0.f);
                    } else if (MODE == MODE_WRITE) {
                        const int col = cb + nf*8;
                        float2 lh = *(const float2*)&g_leaf_h[(size_t)r * DD + col];
                        float2 cw = *(const float2*)&g_ctrl_Wh[bb * DD + col];
                        { float cd = sigmoidf_(d0 + cw.x);
                          float wv = u*cd + (1.f-u)*lh.x; d0 = at*wv + (1.f-at)*lh.x; }
                        { float cd = sigmoidf_(d1 + cw.y);
                          float wv = u*cd + (1.f-u)*lh.y; d1 = at*wv + (1.f-at)*lh.y; }
                    }
                    *(float2*)(crow + nf*8) = make_float2(d0, d1);
                }
            }
        }
    }
}

// ============================================================================
// fp32 split-K GEMM (exact; for M=64 GEMMs: ctrl_Wh, LSTM z)
// ============================================================================
template<int MODE>
__global__ void __launch_bounds__(256, 2)
gemm128(float* __restrict__ C, const float* __restrict__ A,
        const float* __restrict__ Bmat, int M, int N, int K, int kChunk)
{
    __shared__ float As[2][16][136];
    __shared__ float Bs[2][16][128];

    const int tid  = threadIdx.x;
    const int row0 = blockIdx.y * 128;
    const int col0 = blockIdx.x * 128;
    const int ty = tid >> 4;
    const int tx = tid & 15;
    const int a_r = tid >> 1;
    const int a_k = (tid & 1) * 8;
    const int b_k = tid >> 4;
    const int b_n = (tid & 15) * 8;

    const int  kBeg  = blockIdx.z * kChunk;
    const int  nIter = kChunk >> 4;
    const bool a_ok  = (row0 + a_r) < M;

    const float* Aptr = A + (size_t)(row0 + a_r) * K + kBeg + a_k;
    const float* Bptr = Bmat + (size_t)(kBeg + b_k) * N + col0 + b_n;

    float acc[8][8];
    #pragma unroll
    for (int i = 0; i < 8; i++)
        #pragma unroll
        for (int j = 0; j < 8; j++) acc[i][j] = 0.0f;

    float a_st[8], b_st[8];
    {
        float4 v0 = make_float4(0,0,0,0), v1 = v0;
        if (a_ok) { v0 = *(const float4*)(Aptr); v1 = *(const float4*)(Aptr + 4); }
        a_st[0]=v0.x; a_st[1]=v0.y; a_st[2]=v0.z; a_st[3]=v0.w;
        a_st[4]=v1.x; a_st[5]=v1.y; a_st[6]=v1.z; a_st[7]=v1.w;
        float4 w0 = *(const float4*)(Bptr);
        float4 w1 = *(const float4*)(Bptr + 4);
        b_st[0]=w0.x; b_st[1]=w0.y; b_st[2]=w0.z; b_st[3]=w0.w;
        b_st[4]=w1.x; b_st[5]=w1.y; b_st[6]=w1.z; b_st[7]=w1.w;
    }
    #pragma unroll
    for (int i = 0; i < 8; i++) As[0][a_k + i][a_r] = a_st[i];
    *(float4*)&Bs[0][b_k][b_n]     = make_float4(b_st[0], b_st[1], b_st[2], b_st[3]);
    *(float4*)&Bs[0][b_k][b_n + 4] = make_float4(b_st[4], b_st[5], b_st[6], b_st[7]);
    __syncthreads();

    int buf = 0;
    for (int t = 0; t < nIter; t++) {
        if (t + 1 < nIter) {
            float4 v0 = make_float4(0,0,0,0), v1 = v0;
            if (a_ok) { v0 = *(const float4*)(Aptr + (t+1)*16);
                        v1 = *(const float4*)(Aptr + (t+1)*16 + 4); }
            a_st[0]=v0.x; a_st[1]=v0.y; a_st[2]=v0.z; a_st[3]=v0.w;
            a_st[4]=v1.x; a_st[5]=v1.y; a_st[6]=v1.z; a_st[7]=v1.w;
            float4 w0 = *(const float4*)(Bptr + (size_t)(t+1)*16*N);
            float4 w1 = *(const float4*)(Bptr + (size_t)(t+1)*16*N + 4);
            b_st[0]=w0.x; b_st[1]=w0.y; b_st[2]=w0.z; b_st[3]=w0.w;
            b_st[4]=w1.x; b_st[5]=w1.y; b_st[6]=w1.z; b_st[7]=w1.w;
        }
        #pragma unroll
        for (int kk = 0; kk < 16; kk++) {
            float a[8], b[8];
            *(float4*)(a)     = *(const float4*)&As[buf][kk][ty*8];
            *(float4*)(a + 4) = *(const float4*)&As[buf][kk][ty*8 + 4];
            *(float4*)(b)     = *(const float4*)&Bs[buf][kk][tx*8];
            *(float4*)(b + 4) = *(const float4*)&Bs[buf][kk][tx*8 + 4];
            #pragma unroll
            for (int i = 0; i < 8; i++)
                #pragma unroll
                for (int j = 0; j < 8; j++)
                    acc[i][j] = fmaf(a[i], b[j], acc[i][j]);
        }
        if (t + 1 < nIter) {
            #pragma unroll
            for (int i = 0; i < 8; i++) As[buf^1][a_k + i][a_r] = a_st[i];
            *(float4*)&Bs[buf^1][b_k][b_n]     = make_float4(b_st[0], b_st[1], b_st[2], b_st[3]);
            *(float4*)&Bs[buf^1][b_k][b_n + 4] = make_float4(b_st[4], b_st[5], b_st[6], b_st[7]);
        }
        __syncthreads();
        buf ^= 1;
    }

    float* Cbase = C;
    if (MODE == MODE_PART) Cbase = C + (size_t)blockIdx.z * M * N;

    #pragma unroll
    for (int i = 0; i < 8; i++) {
        int r = row0 + ty*8 + i;
        if (r < M) {
            float* crow = Cbase + (size_t)r * N + col0 + tx*8;
            #pragma unroll
            for (int h = 0; h < 8; h += 4) {
                float4 o = make_float4(acc[i][h], acc[i][h+1], acc[i][h+2], acc[i][h+3]);
                if (MODE == MODE_RELU) {
                    o.x = fmaxf(o.x, 0.0f); o.y = fmaxf(o.y, 0.0f);
                    o.z = fmaxf(o.z, 0.0f); o.w = fmaxf(o.w, 0.0f);
                }
                *(float4*)(crow + h) = o;
            }
        }
    }
}

// ---- deterministic split-K reduction (+ optional relu) ----
template<int ACT>
__global__ void reduce_kernel(float* __restrict__ dst, const float* __restrict__ part,
                              int S, int n4)
{
    int i = blockIdx.x * blockDim.x + threadIdx.x;
    if (i >= n4) return;
    const float4* p = (const float4*)part;
    float4 s = p[i];
    for (int k = 1; k < S; k++) {
        float4 v = p[(size_t)k * n4 + i];
        s.x += v.x; s.y += v.y; s.z += v.z; s.w += v.w;
    }
    if (ACT == 1) {
        s.x = fmaxf(s.x, 0.0f); s.y = fmaxf(s.y, 0.0f);
        s.z = fmaxf(s.z, 0.0f); s.w = fmaxf(s.w, 0.0f);
    }
    ((float4*)dst)[i] = s;
}

// ---- per-batch control dot products: ctrl.W_s[512:], ctrl.W_T[512:] ----
__global__ void ctrl_kernel(const float* __restrict__ h0,
                            const float* __restrict__ Ws,
                            const float* __restrict__ WT)
{
    int b = blockIdx.x;
    int lane = threadIdx.x;
    float s1 = 0.0f, s2 = 0.0f;
    for (int u = lane; u < UU; u += 32) {
        float h = h0[b * UU + u];
        s1 += h * Ws[DD + u];
        s2 += h * WT[DD + u];
    }
    #pragma unroll
    for (int o = 16; o; o >>= 1) {
        s1 += __shfl_xor_sync(0xffffffffu, s1, o);
        s2 += __shfl_xor_sync(0xffffffffu, s2, o);
    }
    if (lane == 0) { g_ctrl_s[b] = s1; g_ctrl_T[b] = s2; }
}

// ---- search gates mr for all 255*B internal nodes (warp per node) ----
__global__ void mr_kernel(const float* __restrict__ Ws)
{
    int gw = (blockIdx.x * blockDim.x + threadIdx.x) >> 5;
    int lane = threadIdx.x & 31;
    if (gw >= NROWS_LVL) return;
    const float* row = g_levels + (size_t)gw * DD;
    float s = 0.0f;
    #pragma unroll 4
    for (int k = lane; k < DD; k += 32) s += row[k] * Ws[k];
    #pragma unroll
    for (int o = 16; o; o >>= 1) s += __shfl_xor_sync(0xffffffffu, s, o);
    if (lane == 0) {
        int l = 1;
        #pragma unroll
        for (int i = 2; i <= 8; i++) if (gw >= c_lvl_off[i]) l = i;
        int b = (gw - c_lvl_off[l]) / c_lvl_m[l];
        g_mr[gw] = sigmoidf_(s + g_ctrl_s[b]);
    }
}

// ---- leaf attention: product of 8 path-gate factors ----
__global__ void attn_kernel()
{
    int b = blockIdx.x;
    int leaf = threadIdx.x;
    float a = 1.0f;
    #pragma unroll
    for (int l = 1; l <= 8; l++) {
        int m = NL >> l;
        int j = leaf >> l;
        int c = leaf >> (l - 1);
        float mr = g_mr[c_lvl_off[l] + b * m + j];
        a *= (c & 1) ? mr : (1.0f - mr);
    }
    g_attn[b * NL + leaf] = a;
}

// ---- tree_out[b,e] = sum_n attn[b,n] * inputs[b,n,e] ----
__global__ void treeout_kernel(const float* __restrict__ inputs)
{
    __shared__ float sa[NL];
    int b = blockIdx.x;
    int e = threadIdx.x;
    if (e < NL) sa[e] = g_attn[b * NL + e];
    __syncthreads();
    float s = 0.0f;
    const float* base = inputs + (size_t)b * NL * EE + e;
    #pragma unroll 4
    for (int n = 0; n < NL; n++) s += sa[n] * base[(size_t)n * EE];
    g_tree_out[b * EE + e] = s;
}

// ---- write gate upd per leaf row (warp per row) ----
__global__ void upd_kernel(const float* __restrict__ WT)
{
    int gw = (blockIdx.x * blockDim.x + threadIdx.x) >> 5;
    int lane = threadIdx.x & 31;
    if (gw >= NROWS_LEAF) return;
    const float* row = g_leaf_h + (size_t)gw * DD;
    float s = 0.0f;
    #pragma unroll 4
    for (int k = lane; k < DD; k += 32) s += row[k] * WT[k];
    #pragma unroll
    for (int o = 16; o; o >>= 1) s += __shfl_xor_sync(0xffffffffu, s, o);
    if (lane == 0) g_upd[gw] = sigmoidf_(s + g_ctrl_T[gw >> 8]);
}

// ---- LSTM gates -> h_new, c_new (bias folded in here) ----
__global__ void lstmgate_kernel(const float* __restrict__ c0,
                                const float* __restrict__ bias,
                                float* __restrict__ out_h,
                                float* __restrict__ out_c)
{
    int b = blockIdx.x;
    int u = threadIdx.x;
    float zi = g_z[b * 2048 + u]        + bias[u];
    float zf = g_z[b * 2048 + 512 + u]  + bias[512 + u];
    float zg = g_z[b * 2048 + 1024 + u] + bias[1024 + u];
    float zo = g_z[b * 2048 + 1536 + u] + bias[1536 + u];
    float c = sigmoidf_(zf) * c0[b * UU + u] + sigmoidf_(zi) * tanhf(zg);
    float h = sigmoidf_(zo) * tanhf(c);
    out_h[b * UU + u] = h;
    out_c[b * UU + u] = c;
}

// ============================================================================
extern "C" void kernel_launch(void* const* d_in, const int* in_sizes, int n_in,
                              void* d_out, int out_size)
{
    const float* inputs = (const float*)d_in[0];
    const float* h0     = (const float*)d_in[1];
    const float* c0     = (const float*)d_in[2];
    const float* W_t    = (const float*)d_in[3];
    const float* W_j    = (const float*)d_in[4];
    const float* W_s    = (const float*)d_in[5];
    const float* W_h    = (const float*)d_in[6];
    const float* W_T    = (const float*)d_in[7];
    const float* kern   = (const float*)d_in[8];
    const float* rec    = (const float*)d_in[9];
    const float* bias   = (const float*)d_in[10];

    float* out      = (float*)d_out;
    float* out_h    = out;
    float* out_c    = out + BB * UU;
    float* out_leaf = out + 2 * BB * UU;

    float *p_leaf, *p_levels, *p_part, *p_ctrlWh, *p_z, *p_tree;
    cudaGetSymbolAddress((void**)&p_leaf,   g_leaf_h);
    cudaGetSymbolAddress((void**)&p_levels, g_levels);
    cudaGetSymbolAddress((void**)&p_part,   g_part);
    cudaGetSymbolAddress((void**)&p_ctrlWh, g_ctrl_Wh);
    cudaGetSymbolAddress((void**)&p_z,      g_z);
    cudaGetSymbolAddress((void**)&p_tree,   g_tree_out);

    __nv_bfloat16 *wt_h, *wt_l, *wj_h, *wj_l, *wh_h, *wh_l;
    cudaGetSymbolAddress((void**)&wt_h, g_wt_h);
    cudaGetSymbolAddress((void**)&wt_l, g_wt_l);
    cudaGetSymbolAddress((void**)&wj_h, g_wj_h);
    cudaGetSymbolAddress((void**)&wj_l, g_wj_l);
    cudaGetSymbolAddress((void**)&wh_h, g_wh_h);
    cudaGetSymbolAddress((void**)&wh_l, g_wh_l);

    dim3 blk(256);
    dim3 wblk(32, 8);
    const int lvl_off[10] = {0, 0, 8192, 12288, 14336, 15360, 15872, 16128, 16256, 16320};

    // 0) pre-convert weights to [n][k] bf16 hi/lo planes
    wconv_kernel<<<dim3(512/32, 512/32),  wblk>>>(W_t, wt_h, wt_l, 512,  512);
    wconv_kernel<<<dim3(512/32, 1024/32), wblk>>>(W_j, wj_h, wj_l, 1024, 512);
    wconv_kernel<<<dim3(512/32, 512/32),  wblk>>>(W_h, wh_h, wh_l, 512,  512);

    // 1) leaf embed: relu(inputs @ W_t)  [16384,512]x[512,512]
    mma_gemm2<MODE_RELU><<<dim3(DD/128, NROWS_LEAF/128, 1), blk>>>(
        p_leaf, inputs, wt_h, wt_l, NROWS_LEAF, DD, EE, EE);

    // 2) join level 1 (M=8192, K=1024): direct relu GEMM
    mma_gemm2<MODE_RELU><<<dim3(DD/128, (BB*(NL>>1))/128, 1), blk>>>(
        p_levels, p_leaf, wj_h, wj_l, BB*(NL>>1), DD, 2*DD, 2*DD);

    // 3) join levels 2..8: split-K + deterministic relu reduce
    //    partial footprint = S * Mrows * 512 floats; max = 4,194,304 (lvl 2 & 3)
    const int splitS[9] = {0, 1, 2, 4, 8, 16, 16, 32, 32};
    const float* src = p_levels;
    for (int l = 2; l <= 8; l++) {
        int Mrows = BB * (NL >> l);
        int S     = splitS[l];
        int chunk = (2*DD) / S;
        float* dst = p_levels + (size_t)lvl_off[l] * DD;
        mma_gemm2<MODE_PART><<<dim3(DD/128, (Mrows + 127)/128, S), blk>>>(
            p_part, src, wj_h, wj_l, Mrows, DD, 2*DD, chunk);
        int n4 = (Mrows * DD) / 4;
        reduce_kernel<1><<<(n4 + 255)/256, 256>>>(dst, p_part, S, n4);
        src = dst;
    }

    // 4) per-batch control terms; ctrl_Wh = h0 @ W_h[512:,:] (EXACT fp32 split-K)
    ctrl_kernel<<<BB, 32>>>(h0, W_s, W_T);
    gemm128<MODE_PART><<<dim3(DD/128, 1, 8), blk>>>(
        p_part, h0, W_h + DD*DD, BB, DD, UU, UU/8);
    reduce_kernel<0><<<(BB*DD/4 + 255)/256, 256>>>(p_ctrlWh, p_part, 8, BB*DD/4);

    // 5) search gates, attentions, retrieval, write gates
    mr_kernel<<<(NROWS_LVL * 32 + 255)/256, 256>>>(W_s);
    attn_kernel<<<BB, NL>>>();
    treeout_kernel<<<BB, EE>>>(inputs);
    upd_kernel<<<(NROWS_LEAF * 32 + 255)/256, 256>>>(W_T);

    // 6) fused write-update GEMM straight into d_out
    mma_gemm2<MODE_WRITE><<<dim3(DD/128, NROWS_LEAF/128, 1), blk>>>(
        out_leaf, p_leaf, wh_h, wh_l, NROWS_LEAF, DD, DD, DD);

    // 7) LSTM z (EXACT fp32 split-K): tree_out@kernel -> parts 0..7,
    //    h0@rec_kernel -> parts 8..15, reduce S=16, then gates (+bias)
    gemm128<MODE_PART><<<dim3(4*UU/128, 1, 8), blk>>>(
        p_part, p_tree, kern, BB, 4*UU, EE, EE/8);
    gemm128<MODE_PART><<<dim3(4*UU/128, 1, 8), blk>>>(
        p_part + (size_t)8 * BB * 4*UU, h0, rec, BB, 4*UU, UU, UU/8);
    reduce_kernel<0><<<(BB*4*UU/4 + 255)/256, 256>>>(p_z, p_part, 16, BB*4*UU/4);
    lstmgate_kernel<<<BB, UU>>>(c0, bias, out_h, out_c);
}